// round 15
// baseline (speedup 1.0000x reference)
#include <cuda_runtime.h>
#include <cuda_bf16.h>
#include <cstdint>

#define BATCH 4
#define SEQ 2048
#define DM 1024
#define NH 16
#define DK 64

// ---------------------------------------------------------------------------
// scratch (allocation-free rule: __device__ globals)
// ---------------------------------------------------------------------------
__device__ __nv_bfloat16 g_qhi[BATCH * SEQ * DM];   // 16 MB (split Q-proj out)
__device__ __nv_bfloat16 g_qlo[BATCH * SEQ * DM];
__device__ __nv_bfloat16 g_khi[BATCH * SEQ * DK];   // 1 MB  (split K)
__device__ __nv_bfloat16 g_klo[BATCH * SEQ * DK];
__device__ __nv_bfloat16 g_vthi[BATCH * DK * SEQ];  // 1 MB  (split V^T)
__device__ __nv_bfloat16 g_vtlo[BATCH * DK * SEQ];
__device__ __nv_bfloat16 g_ahi[BATCH * SEQ * DM];   // 16 MB (split activations)
__device__ __nv_bfloat16 g_alo[BATCH * SEQ * DM];   // 16 MB
__device__ __nv_bfloat16 g_wqt_hi[DM * DM];         // 2 MB (transposed weights)
__device__ __nv_bfloat16 g_wqt_lo[DM * DM];
__device__ __nv_bfloat16 g_wot_hi[DM * DM];
__device__ __nv_bfloat16 g_wot_lo[DM * DM];

__device__ __forceinline__ float ex2_fast(float x) {
    float r;
    asm("ex2.approx.ftz.f32 %0, %1;" : "=f"(r) : "f"(x));
    return r;
}

__device__ __forceinline__ uint32_t smem_u32(const void* p) {
    uint32_t a;
    asm("{ .reg .u64 t; cvta.to.shared.u64 t, %1; cvt.u32.u64 %0, t; }"
        : "=r"(a) : "l"(p));
    return a;
}

__device__ __forceinline__ void cp_async16(uint32_t saddr, const void* g) {
    asm volatile("cp.async.cg.shared.global [%0], [%1], 16;"
                 :: "r"(saddr), "l"(g));
}
#define CP_COMMIT() asm volatile("cp.async.commit_group;" ::: "memory")
#define CP_WAIT1()  asm volatile("cp.async.wait_group 1;" ::: "memory")
#define CP_WAIT0()  asm volatile("cp.async.wait_group 0;" ::: "memory")

__device__ __forceinline__ void ldsm_x4(uint32_t (&r)[4], uint32_t addr) {
    asm volatile(
        "ldmatrix.sync.aligned.m8n8.x4.shared.b16 {%0,%1,%2,%3}, [%4];"
        : "=r"(r[0]), "=r"(r[1]), "=r"(r[2]), "=r"(r[3]) : "r"(addr));
}

__device__ __forceinline__ void ldsm_x2(uint32_t (&r)[2], uint32_t addr) {
    asm volatile(
        "ldmatrix.sync.aligned.m8n8.x2.shared.b16 {%0,%1}, [%2];"
        : "=r"(r[0]), "=r"(r[1]) : "r"(addr));
}

__device__ __forceinline__ void mma_bf16(float (&d)[4], const uint32_t (&a)[4],
                                         const uint32_t (&b)[2]) {
    asm volatile(
        "mma.sync.aligned.m16n8k16.row.col.f32.bf16.bf16.f32 "
        "{%0,%1,%2,%3}, {%4,%5,%6,%7}, {%8,%9}, {%0,%1,%2,%3};"
        : "+f"(d[0]), "+f"(d[1]), "+f"(d[2]), "+f"(d[3])
        : "r"(a[0]), "r"(a[1]), "r"(a[2]), "r"(a[3]), "r"(b[0]), "r"(b[1]));
}

__device__ __forceinline__ uint32_t pack_bf16(__nv_bfloat16 lo, __nv_bfloat16 hi) {
    __nv_bfloat162 t(lo, hi);
    return *(uint32_t*)&t;
}

// ---------------------------------------------------------------------------
// Split fp32 -> (hi, lo) bf16, elementwise (vectorized by 4)
// ---------------------------------------------------------------------------
__global__ __launch_bounds__(256) void split_convert_kernel(
    const float* __restrict__ in, __nv_bfloat16* __restrict__ hi,
    __nv_bfloat16* __restrict__ lo, int n4) {
    int i = blockIdx.x * blockDim.x + threadIdx.x;
    if (i >= n4) return;
    float4 x = ((const float4*)in)[i];
    __nv_bfloat16 h0 = __float2bfloat16(x.x);
    __nv_bfloat16 h1 = __float2bfloat16(x.y);
    __nv_bfloat16 h2 = __float2bfloat16(x.z);
    __nv_bfloat16 h3 = __float2bfloat16(x.w);
    __nv_bfloat16 l0 = __float2bfloat16(x.x - __bfloat162float(h0));
    __nv_bfloat16 l1 = __float2bfloat16(x.y - __bfloat162float(h1));
    __nv_bfloat16 l2 = __float2bfloat16(x.z - __bfloat162float(h2));
    __nv_bfloat16 l3 = __float2bfloat16(x.w - __bfloat162float(h3));
    __nv_bfloat162* hp = (__nv_bfloat162*)hi;
    __nv_bfloat162* lp = (__nv_bfloat162*)lo;
    hp[2 * i]     = __nv_bfloat162(h0, h1);
    hp[2 * i + 1] = __nv_bfloat162(h2, h3);
    lp[2 * i]     = __nv_bfloat162(l0, l1);
    lp[2 * i + 1] = __nv_bfloat162(l2, l3);
}

// ---------------------------------------------------------------------------
// Transpose + split (+ optional scale): in [K, N] fp32 -> hi/lo [N, K] bf16
// ---------------------------------------------------------------------------
__global__ __launch_bounds__(256) void transpose_split_kernel(
    const float* __restrict__ in, __nv_bfloat16* __restrict__ hi,
    __nv_bfloat16* __restrict__ lo, int K, int N, float scale) {
    __shared__ float t[32][33];
    int n0 = blockIdx.x * 32, k0 = blockIdx.y * 32;
    int tx = threadIdx.x, ty = threadIdx.y;
#pragma unroll
    for (int j = 0; j < 4; j++)
        t[ty + 8 * j][tx] = in[(size_t)(k0 + ty + 8 * j) * N + n0 + tx];
    __syncthreads();
#pragma unroll
    for (int j = 0; j < 4; j++) {
        float x = t[tx][ty + 8 * j] * scale;
        __nv_bfloat16 h = __float2bfloat16(x);
        __nv_bfloat16 l = __float2bfloat16(x - __bfloat162float(h));
        size_t o = (size_t)(n0 + ty + 8 * j) * K + k0 + tx;
        hi[o] = h;
        lo[o] = l;
    }
}

// ---------------------------------------------------------------------------
// mma.sync bf16 split-precision GEMM, cp.async double-buffered, all-ks
// fragment preload. Epilogue: fp32 C (Chi==nullptr) or split-bf16 Chi/Clo.
// ---------------------------------------------------------------------------
#define SPAD 40
#define GARR (128 * SPAD)                    // bf16 elements per array
#define GEMM_SMEM (2 * 4 * GARR * 2)         // 81920 bytes

__global__ __launch_bounds__(256, 1) void mma_sync_gemm(
    const __nv_bfloat16* __restrict__ Ah, const __nv_bfloat16* __restrict__ Al,
    const __nv_bfloat16* __restrict__ Bh, const __nv_bfloat16* __restrict__ Bl,
    float* __restrict__ C, __nv_bfloat16* __restrict__ Chi,
    __nv_bfloat16* __restrict__ Clo, int Kd, int Nd) {
    extern __shared__ __align__(16) __nv_bfloat16 gsm[];

    const int tid = threadIdx.x;
    const int wid = tid / 32, lane = tid % 32;
    const int wm = wid / 4, wn = wid % 4;
    const int mBase = blockIdx.y * 128;
    const int nBase = blockIdx.x * 128;
    const int nChunks = Kd / 32;

    float acc[4][4][4];
#pragma unroll
    for (int i = 0; i < 4; i++)
#pragma unroll
        for (int j = 0; j < 4; j++)
#pragma unroll
            for (int r = 0; r < 4; r++) acc[i][j][r] = 0.0f;

    const int a_row = lane % 16, a_col8 = (lane / 16) * 8;
    const int b_row = lane % 8, b_col8 = ((lane % 16) / 8) * 8;

    auto load_stage = [&](int c, int s) {
        __nv_bfloat16* st = gsm + s * 4 * GARR;
        const int kBase = c * 32;
#pragma unroll
        for (int i = tid; i < 512; i += 256) {
            const int r = i >> 2, q = i & 3;
            const size_t ga = (size_t)(mBase + r) * Kd + kBase + q * 8;
            const size_t gb = (size_t)(nBase + r) * Kd + kBase + q * 8;
            const int so = r * SPAD + q * 8;
            cp_async16(smem_u32(&st[so]), &Ah[ga]);
            cp_async16(smem_u32(&st[GARR + so]), &Al[ga]);
            cp_async16(smem_u32(&st[2 * GARR + so]), &Bh[gb]);
            cp_async16(smem_u32(&st[3 * GARR + so]), &Bl[gb]);
        }
    };

    load_stage(0, 0);
    CP_COMMIT();

    for (int c = 0; c < nChunks; ++c) {
        if (c + 1 < nChunks) {
            load_stage(c + 1, (c + 1) & 1);
            CP_COMMIT();
            CP_WAIT1();
        } else {
            CP_WAIT0();
        }
        __syncthreads();

        const __nv_bfloat16* st = gsm + (c & 1) * 4 * GARR;
        const __nv_bfloat16* sAh = st;
        const __nv_bfloat16* sAl = st + GARR;
        const __nv_bfloat16* sBh = st + 2 * GARR;
        const __nv_bfloat16* sBl = st + 3 * GARR;

        // preload ALL fragments for both ks steps, then MMA
        uint32_t afh[2][4][4], afl[2][4][4];
        uint32_t bfh[2][4][2], bfl[2][4][2];
#pragma unroll
        for (int ks = 0; ks < 2; ++ks) {
            const int kk = ks * 16;
#pragma unroll
            for (int mt = 0; mt < 4; mt++) {
                const int row = wm * 64 + mt * 16 + a_row;
                ldsm_x4(afh[ks][mt], smem_u32(&sAh[row * SPAD + kk + a_col8]));
                ldsm_x4(afl[ks][mt], smem_u32(&sAl[row * SPAD + kk + a_col8]));
            }
#pragma unroll
            for (int nt = 0; nt < 4; nt++) {
                const int row = wn * 32 + nt * 8 + b_row;
                ldsm_x2(bfh[ks][nt], smem_u32(&sBh[row * SPAD + kk + b_col8]));
                ldsm_x2(bfl[ks][nt], smem_u32(&sBl[row * SPAD + kk + b_col8]));
            }
        }
#pragma unroll
        for (int ks = 0; ks < 2; ++ks)
#pragma unroll
            for (int mt = 0; mt < 4; mt++)
#pragma unroll
                for (int nt = 0; nt < 4; nt++) {
                    mma_bf16(acc[mt][nt], afh[ks][mt], bfh[ks][nt]);
                    mma_bf16(acc[mt][nt], afh[ks][mt], bfl[ks][nt]);
                    mma_bf16(acc[mt][nt], afl[ks][mt], bfh[ks][nt]);
                }
        __syncthreads();
    }

    const int em = lane / 4, en = 2 * (lane % 4);
    if (Chi == nullptr) {
#pragma unroll
        for (int mt = 0; mt < 4; mt++) {
#pragma unroll
            for (int nt = 0; nt < 4; nt++) {
                const int m0 = mBase + wm * 64 + mt * 16 + em;
                const int n0 = nBase + wn * 32 + nt * 8 + en;
                *(float2*)&C[(size_t)m0 * Nd + n0] =
                    make_float2(acc[mt][nt][0], acc[mt][nt][1]);
                *(float2*)&C[(size_t)(m0 + 8) * Nd + n0] =
                    make_float2(acc[mt][nt][2], acc[mt][nt][3]);
            }
        }
    } else {
#pragma unroll
        for (int mt = 0; mt < 4; mt++) {
#pragma unroll
            for (int nt = 0; nt < 4; nt++) {
                const int m0 = mBase + wm * 64 + mt * 16 + em;
                const int n0 = nBase + wn * 32 + nt * 8 + en;
                const float x0 = acc[mt][nt][0], x1 = acc[mt][nt][1];
                const float x2 = acc[mt][nt][2], x3 = acc[mt][nt][3];
                const __nv_bfloat16 h0 = __float2bfloat16(x0);
                const __nv_bfloat16 h1 = __float2bfloat16(x1);
                const __nv_bfloat16 h2 = __float2bfloat16(x2);
                const __nv_bfloat16 h3 = __float2bfloat16(x3);
                *(uint32_t*)&Chi[(size_t)m0 * Nd + n0] = pack_bf16(h0, h1);
                *(uint32_t*)&Chi[(size_t)(m0 + 8) * Nd + n0] = pack_bf16(h2, h3);
                *(uint32_t*)&Clo[(size_t)m0 * Nd + n0] =
                    pack_bf16(__float2bfloat16(x0 - __bfloat162float(h0)),
                              __float2bfloat16(x1 - __bfloat162float(h1)));
                *(uint32_t*)&Clo[(size_t)(m0 + 8) * Nd + n0] =
                    pack_bf16(__float2bfloat16(x2 - __bfloat162float(h2)),
                              __float2bfloat16(x3 - __bfloat162float(h3)));
            }
        }
    }
}

// ---------------------------------------------------------------------------
// Fused K/V projection (SIMT fp32) with split-bf16 epilogue.
// z=0: K@w_k -> khi/klo [b*SEQ][DK]
// z=1: V@w_v -> vthi/vtlo [b][DK][SEQ] (transposed for attention's P@V)
// ---------------------------------------------------------------------------
__global__ __launch_bounds__(128) void kv_proj_kernel(
    const float* __restrict__ Kin, const float* __restrict__ Vin,
    const float* __restrict__ w_k, const float* __restrict__ w_v,
    __nv_bfloat16* __restrict__ khi, __nv_bfloat16* __restrict__ klo,
    __nv_bfloat16* __restrict__ vthi, __nv_bfloat16* __restrict__ vtlo) {
    constexpr int BM = 128, BN = 64, BK = 8, TM = 8, TN = 8;
    constexpr int NT = (BM / TM) * (BN / TN);
    __shared__ float As[BK][BM];
    __shared__ float Bs[BK][BN];

    const int isV = blockIdx.z;
    const float* A  = isV ? Vin : Kin;
    const float* Bm = isV ? w_v : w_k;

    const int tid = threadIdx.x;
    const int tx = tid % (BN / TN);
    const int ty = tid / (BN / TN);
    const int mBase = blockIdx.y * BM;
    const int K = DM, Nn = DK;

    float acc[TM][TN];
#pragma unroll
    for (int i = 0; i < TM; i++)
#pragma unroll
        for (int j = 0; j < TN; j++) acc[i][j] = 0.0f;

    for (int k0 = 0; k0 < K; k0 += BK) {
#pragma unroll
        for (int i = tid; i < BM * BK / 4; i += NT) {
            int r = i / (BK / 4);
            int c4 = i % (BK / 4);
            float4 a = *(const float4*)&A[(size_t)(mBase + r) * K + k0 + c4 * 4];
            As[c4 * 4 + 0][r] = a.x;
            As[c4 * 4 + 1][r] = a.y;
            As[c4 * 4 + 2][r] = a.z;
            As[c4 * 4 + 3][r] = a.w;
        }
#pragma unroll
        for (int i = tid; i < BK * BN / 4; i += NT) {
            int r = i / (BN / 4);
            int c4 = i % (BN / 4);
            *(float4*)&Bs[r][c4 * 4] =
                *(const float4*)&Bm[(size_t)(k0 + r) * Nn + c4 * 4];
        }
        __syncthreads();

#pragma unroll
        for (int kk = 0; kk < BK; kk++) {
            float ra[TM], rb[TN];
#pragma unroll
            for (int i = 0; i < TM; i++) ra[i] = As[kk][ty * TM + i];
#pragma unroll
            for (int j = 0; j < TN; j++) rb[j] = Bs[kk][tx * TN + j];
#pragma unroll
            for (int i = 0; i < TM; i++)
#pragma unroll
                for (int j = 0; j < TN; j++) acc[i][j] += ra[i] * rb[j];
        }
        __syncthreads();
    }

    // split-bf16 epilogue (K row-major; V transposed)
#pragma unroll
    for (int i = 0; i < TM; i++) {
        const int s = mBase + ty * TM + i;       // global row: b*SEQ + n
#pragma unroll
        for (int j = 0; j < TN; j++) {
            const int col = tx * TN + j;         // dk index
            const float x = acc[i][j];
            const __nv_bfloat16 hv = __float2bfloat16(x);
            const __nv_bfloat16 lv = __float2bfloat16(x - __bfloat162float(hv));
            if (!isV) {
                khi[(size_t)s * DK + col] = hv;
                klo[(size_t)s * DK + col] = lv;
            } else {
                const int bb = s / SEQ, n = s % SEQ;
                vthi[((size_t)bb * DK + col) * SEQ + n] = hv;
                vtlo[((size_t)bb * DK + col) * SEQ + n] = lv;
            }
        }
    }
}

// ---------------------------------------------------------------------------
// Causal MQA flash attention (mma.sync, split-bf16), cp.async double-buffered
// K/V tiles, pre-split Q (scale folded into w_q). Writes split-bf16 ahi/alo.
// ---------------------------------------------------------------------------
#define APAD 72
#define KVARR (64 * APAD)                              // bf16 per array
#define Q_BYTES (2 * 128 * APAD * 2)                   // 36864
#define ATTN_SMEM (Q_BYTES + 2 * 4 * KVARR * 2)        // 110592

__global__ __launch_bounds__(256, 1) void mqa_attn_mma(
    const __nv_bfloat16* __restrict__ qhi, const __nv_bfloat16* __restrict__ qlo,
    const __nv_bfloat16* __restrict__ khi, const __nv_bfloat16* __restrict__ klo,
    const __nv_bfloat16* __restrict__ vthi, const __nv_bfloat16* __restrict__ vtlo,
    __nv_bfloat16* __restrict__ outhi, __nv_bfloat16* __restrict__ outlo) {
    extern __shared__ __align__(16) char smem_raw[];
    __nv_bfloat16* sQh = (__nv_bfloat16*)smem_raw;
    __nv_bfloat16* sQl = sQh + 128 * APAD;
    __nv_bfloat16* sKV = sQl + 128 * APAD;  // 2 stages x {Kh, Kl, Vh, Vl}

    const int qt = gridDim.x - 1 - blockIdx.x;  // heavy qtiles first
    const int h = blockIdx.y, b = blockIdx.z;
    const int tid = threadIdx.x, wid = tid / 32, lane = tid % 32;
    const int rowBase = qt * 128;
    const int wRow = wid * 16;

    // ---- copy pre-split Q slice [128][64] (scale already folded) ----
    {
        const __nv_bfloat16* qh = &qhi[((size_t)b * SEQ + rowBase) * DM + h * DK];
        const __nv_bfloat16* ql = &qlo[((size_t)b * SEQ + rowBase) * DM + h * DK];
#pragma unroll
        for (int i = tid; i < 1024; i += 256) {
            const int r = i >> 3, c = (i & 7) * 8;
            *(uint4*)&sQh[r * APAD + c] = *(const uint4*)&qh[(size_t)r * DM + c];
            *(uint4*)&sQl[r * APAD + c] = *(const uint4*)&ql[(size_t)r * DM + c];
        }
    }

    // async-load K/V tile t into stage s (no sync here)
    auto load_kv = [&](int t, int s) {
        __nv_bfloat16* st = sKV + s * 4 * KVARR;
        const __nv_bfloat16* kh = &khi[((size_t)b * SEQ + t * 64) * DK];
        const __nv_bfloat16* kl = &klo[((size_t)b * SEQ + t * 64) * DK];
        const __nv_bfloat16* vh = &vthi[(size_t)b * DK * SEQ + t * 64];
        const __nv_bfloat16* vl = &vtlo[(size_t)b * DK * SEQ + t * 64];
#pragma unroll
        for (int i = tid; i < 512; i += 256) {
            const int r = i >> 3, c = (i & 7) * 8;
            const int so = r * APAD + c;
            cp_async16(smem_u32(&st[so]), &kh[r * DK + c]);
            cp_async16(smem_u32(&st[KVARR + so]), &kl[r * DK + c]);
            cp_async16(smem_u32(&st[2 * KVARR + so]), &vh[(size_t)r * SEQ + c]);
            cp_async16(smem_u32(&st[3 * KVARR + so]), &vl[(size_t)r * SEQ + c]);
        }
    };

    const int nT = 2 * qt + 2;
    load_kv(0, 0);
    CP_COMMIT();
    __syncthreads();  // Q smem ready for all warps

    // ---- preload Q fragments for all 4 k-steps ----
    uint32_t qfh[4][4], qfl[4][4];
    {
        const int rr = wRow + (lane & 7) + ((lane >> 3) & 1) * 8;
        const int cc = (lane >> 4) * 8;
#pragma unroll
        for (int ks = 0; ks < 4; ks++) {
            ldsm_x4(qfh[ks], smem_u32(&sQh[rr * APAD + ks * 16 + cc]));
            ldsm_x4(qfl[ks], smem_u32(&sQl[rr * APAD + ks * 16 + cc]));
        }
    }

    float oacc[8][4];
#pragma unroll
    for (int nt = 0; nt < 8; nt++)
#pragma unroll
        for (int j = 0; j < 4; j++) oacc[nt][j] = 0.0f;
    float m0 = -6e29f, m1 = -6e29f, l0 = 0.0f, l1 = 0.0f;

    const int bRowK = (lane & 7);
    const int bColK = ((lane >> 3) & 1) * 8;

    for (int t = 0; t < nT; ++t) {
        if (t + 1 < nT) {
            load_kv(t + 1, (t + 1) & 1);
            CP_COMMIT();
            CP_WAIT1();
        } else {
            CP_WAIT0();
        }
        __syncthreads();

        const __nv_bfloat16* st = sKV + (t & 1) * 4 * KVARR;
        const __nv_bfloat16* sKh = st;
        const __nv_bfloat16* sKl = st + KVARR;
        const __nv_bfloat16* sVh = st + 2 * KVARR;
        const __nv_bfloat16* sVl = st + 3 * KVARR;

        // ---- S = Q @ K^T (split, 3 terms) ----
        float sacc[8][4];
#pragma unroll
        for (int nt = 0; nt < 8; nt++)
#pragma unroll
            for (int j = 0; j < 4; j++) sacc[nt][j] = 0.0f;
#pragma unroll
        for (int ks = 0; ks < 4; ks++) {
#pragma unroll
            for (int nt = 0; nt < 8; nt++) {
                uint32_t kbh[2], kbl[2];
                ldsm_x2(kbh, smem_u32(&sKh[(nt * 8 + bRowK) * APAD + ks * 16 + bColK]));
                ldsm_x2(kbl, smem_u32(&sKl[(nt * 8 + bRowK) * APAD + ks * 16 + bColK]));
                mma_bf16(sacc[nt], qfh[ks], kbh);
                mma_bf16(sacc[nt], qfh[ks], kbl);
                mma_bf16(sacc[nt], qfl[ks], kbh);
            }
        }

        // ---- causal mask (only near-diagonal tiles) ----
        if (64 * t + 63 > rowBase + wRow) {
            const int r0 = rowBase + wRow + (lane >> 2);
#pragma unroll
            for (int nt = 0; nt < 8; nt++) {
                const int col = 64 * t + nt * 8 + 2 * (lane & 3);
                if (col > r0) sacc[nt][0] = -1e30f;
                if (col + 1 > r0) sacc[nt][1] = -1e30f;
                if (col > r0 + 8) sacc[nt][2] = -1e30f;
                if (col + 1 > r0 + 8) sacc[nt][3] = -1e30f;
            }
        }

        // ---- online softmax in fragments ----
        float rm0 = -1e30f, rm1 = -1e30f;
#pragma unroll
        for (int nt = 0; nt < 8; nt++) {
            rm0 = fmaxf(rm0, fmaxf(sacc[nt][0], sacc[nt][1]));
            rm1 = fmaxf(rm1, fmaxf(sacc[nt][2], sacc[nt][3]));
        }
        rm0 = fmaxf(rm0, __shfl_xor_sync(0xffffffffu, rm0, 1));
        rm0 = fmaxf(rm0, __shfl_xor_sync(0xffffffffu, rm0, 2));
        rm1 = fmaxf(rm1, __shfl_xor_sync(0xffffffffu, rm1, 1));
        rm1 = fmaxf(rm1, __shfl_xor_sync(0xffffffffu, rm1, 2));
        const float mn0 = fmaxf(m0, rm0), mn1 = fmaxf(m1, rm1);
        const float c0 = ex2_fast(m0 - mn0), c1 = ex2_fast(m1 - mn1);
        m0 = mn0; m1 = mn1;
        l0 *= c0; l1 *= c1;
#pragma unroll
        for (int nt = 0; nt < 8; nt++) {
            oacc[nt][0] *= c0; oacc[nt][1] *= c0;
            oacc[nt][2] *= c1; oacc[nt][3] *= c1;
        }

        uint32_t php[8][2], plp[8][2];
#pragma unroll
        for (int nt = 0; nt < 8; nt++) {
            const float p0 = ex2_fast(sacc[nt][0] - m0);
            const float p1 = ex2_fast(sacc[nt][1] - m0);
            const float p2 = ex2_fast(sacc[nt][2] - m1);
            const float p3 = ex2_fast(sacc[nt][3] - m1);
            l0 += p0 + p1;
            l1 += p2 + p3;
            const __nv_bfloat16 b0 = __float2bfloat16(p0), b1 = __float2bfloat16(p1);
            const __nv_bfloat16 b2 = __float2bfloat16(p2), b3 = __float2bfloat16(p3);
            php[nt][0] = pack_bf16(b0, b1);
            php[nt][1] = pack_bf16(b2, b3);
            plp[nt][0] = pack_bf16(__float2bfloat16(p0 - __bfloat162float(b0)),
                                   __float2bfloat16(p1 - __bfloat162float(b1)));
            plp[nt][1] = pack_bf16(__float2bfloat16(p2 - __bfloat162float(b2)),
                                   __float2bfloat16(p3 - __bfloat162float(b3)));
        }

        // ---- O += P @ V (split, 3 terms) ----
#pragma unroll
        for (int t2 = 0; t2 < 4; t2++) {
            const uint32_t ah[4] = {php[2 * t2][0], php[2 * t2][1],
                                    php[2 * t2 + 1][0], php[2 * t2 + 1][1]};
            const uint32_t al[4] = {plp[2 * t2][0], plp[2 * t2][1],
                                    plp[2 * t2 + 1][0], plp[2 * t2 + 1][1]};
#pragma unroll
            for (int ntd = 0; ntd < 8; ntd++) {
                uint32_t vbh[2], vbl[2];
                ldsm_x2(vbh, smem_u32(&sVh[(ntd * 8 + bRowK) * APAD + t2 * 16 + bColK]));
                ldsm_x2(vbl, smem_u32(&sVl[(ntd * 8 + bRowK) * APAD + t2 * 16 + bColK]));
                mma_bf16(oacc[ntd], ah, vbh);
                mma_bf16(oacc[ntd], ah, vbl);
                mma_bf16(oacc[ntd], al, vbh);
            }
        }
        __syncthreads();  // all warps done with this stage before it is reused
    }

    // ---- finalize: reduce l, normalize, write split-bf16 directly ----
    l0 += __shfl_xor_sync(0xffffffffu, l0, 1);
    l0 += __shfl_xor_sync(0xffffffffu, l0, 2);
    l1 += __shfl_xor_sync(0xffffffffu, l1, 1);
    l1 += __shfl_xor_sync(0xffffffffu, l1, 2);
    const float inv0 = 1.0f / l0, inv1 = 1.0f / l1;
    const int r0 = rowBase + wRow + (lane >> 2);
    const int cb = h * DK + 2 * (lane & 3);
#pragma unroll
    for (int nt = 0; nt < 8; nt++) {
        const float x0 = oacc[nt][0] * inv0, x1 = oacc[nt][1] * inv0;
        const float x2 = oacc[nt][2] * inv1, x3 = oacc[nt][3] * inv1;
        const __nv_bfloat16 h0 = __float2bfloat16(x0), h1 = __float2bfloat16(x1);
        const __nv_bfloat16 h2 = __float2bfloat16(x2), h3 = __float2bfloat16(x3);
        const size_t i0 = ((size_t)b * SEQ + r0) * DM + cb + nt * 8;
        const size_t i1 = ((size_t)b * SEQ + r0 + 8) * DM + cb + nt * 8;
        *(uint32_t*)&outhi[i0] = pack_bf16(h0, h1);
        *(uint32_t*)&outhi[i1] = pack_bf16(h2, h3);
        *(uint32_t*)&outlo[i0] =
            pack_bf16(__float2bfloat16(x0 - __bfloat162float(h0)),
                      __float2bfloat16(x1 - __bfloat162float(h1)));
        *(uint32_t*)&outlo[i1] =
            pack_bf16(__float2bfloat16(x2 - __bfloat162float(h2)),
                      __float2bfloat16(x3 - __bfloat162float(h3)));
    }
}

// ---------------------------------------------------------------------------
extern "C" void kernel_launch(void* const* d_in, const int* in_sizes, int n_in,
                              void* d_out, int out_size) {
    const float* Q   = (const float*)d_in[0];
    const float* K   = (const float*)d_in[1];
    const float* V   = (const float*)d_in[2];
    const float* w_q = (const float*)d_in[3];
    const float* w_k = (const float*)d_in[4];
    const float* w_v = (const float*)d_in[5];
    const float* w_o = (const float*)d_in[6];
    float* out = (float*)d_out;

    __nv_bfloat16 *qhi, *qlo, *khi, *klo, *vthi, *vtlo, *ahi, *alo;
    __nv_bfloat16 *wqh, *wql, *woh, *wol;
    cudaGetSymbolAddress((void**)&qhi, g_qhi);
    cudaGetSymbolAddress((void**)&qlo, g_qlo);
    cudaGetSymbolAddress((void**)&khi, g_khi);
    cudaGetSymbolAddress((void**)&klo, g_klo);
    cudaGetSymbolAddress((void**)&vthi, g_vthi);
    cudaGetSymbolAddress((void**)&vtlo, g_vtlo);
    cudaGetSymbolAddress((void**)&ahi, g_ahi);
    cudaGetSymbolAddress((void**)&alo, g_alo);
    cudaGetSymbolAddress((void**)&wqh, g_wqt_hi);
    cudaGetSymbolAddress((void**)&wql, g_wqt_lo);
    cudaGetSymbolAddress((void**)&woh, g_wot_hi);
    cudaGetSymbolAddress((void**)&wol, g_wot_lo);

    cudaFuncSetAttribute(mma_sync_gemm,
                         cudaFuncAttributeMaxDynamicSharedMemorySize, GEMM_SMEM);
    cudaFuncSetAttribute(mqa_attn_mma,
                         cudaFuncAttributeMaxDynamicSharedMemorySize, ATTN_SMEM);

    const int M = BATCH * SEQ;      // 8192
    const int n4 = M * DM / 4;
    const float sc = 0.125f * 1.44269504088896f;  // 1/sqrt(64) * log2(e)

    // weight transpose + split; softmax scale folded into w_q
    transpose_split_kernel<<<dim3(DM / 32, DM / 32), dim3(32, 8)>>>(
        w_q, wqh, wql, DM, DM, sc);
    transpose_split_kernel<<<dim3(DM / 32, DM / 32), dim3(32, 8)>>>(
        w_o, woh, wol, DM, DM, 1.0f);

    // Q projection (tensor cores): split Q input, MMA -> split qhi/qlo
    split_convert_kernel<<<n4 / 256, 256>>>(Q, ahi, alo, n4);
    mma_sync_gemm<<<dim3(DM / 128, M / 128), 256, GEMM_SMEM>>>(
        ahi, alo, wqh, wql, nullptr, qhi, qlo, DM, DM);

    // K/V projections (SIMT fp32) with fused split / transpose epilogue
    kv_proj_kernel<<<dim3(1, M / 128, 2), 128>>>(K, V, w_k, w_v,
                                                 khi, klo, vthi, vtlo);

    // causal MQA attention on tensor cores; writes split-bf16 ahi/alo
    mqa_attn_mma<<<dim3(SEQ / 128, NH, BATCH), 256, ATTN_SMEM>>>(
        qhi, qlo, khi, klo, vthi, vtlo, ahi, alo);

    // O projection (tensor cores) -> fp32 d_out
    mma_sync_gemm<<<dim3(DM / 128, M / 128), 256, GEMM_SMEM>>>(
        ahi, alo, woh, wol, out, nullptr, nullptr, DM, DM);
}

// round 16
// speedup vs baseline: 1.0631x; 1.0631x over previous
#include <cuda_runtime.h>
#include <cuda_bf16.h>
#include <cstdint>

#define BATCH 4
#define SEQ 2048
#define DM 1024
#define NH 16
#define DK 64

// ---------------------------------------------------------------------------
// scratch (allocation-free rule: __device__ globals)
// ---------------------------------------------------------------------------
__device__ __nv_bfloat16 g_qhi[BATCH * SEQ * DM];   // 16 MB (split Q-proj out)
__device__ __nv_bfloat16 g_qlo[BATCH * SEQ * DM];
__device__ __nv_bfloat16 g_khi[BATCH * SEQ * DK];   // 1 MB  (split K)
__device__ __nv_bfloat16 g_klo[BATCH * SEQ * DK];
__device__ __nv_bfloat16 g_vthi[BATCH * DK * SEQ];  // 1 MB  (split V^T)
__device__ __nv_bfloat16 g_vtlo[BATCH * DK * SEQ];
__device__ __nv_bfloat16 g_ahi[BATCH * SEQ * DM];   // 16 MB (split activations)
__device__ __nv_bfloat16 g_alo[BATCH * SEQ * DM];   // 16 MB
__device__ __nv_bfloat16 g_wqt_hi[DM * DM];         // 2 MB (transposed weights)
__device__ __nv_bfloat16 g_wqt_lo[DM * DM];
__device__ __nv_bfloat16 g_wot_hi[DM * DM];
__device__ __nv_bfloat16 g_wot_lo[DM * DM];

__device__ __forceinline__ float ex2_fast(float x) {
    float r;
    asm("ex2.approx.ftz.f32 %0, %1;" : "=f"(r) : "f"(x));
    return r;
}

__device__ __forceinline__ uint32_t smem_u32(const void* p) {
    uint32_t a;
    asm("{ .reg .u64 t; cvta.to.shared.u64 t, %1; cvt.u32.u64 %0, t; }"
        : "=r"(a) : "l"(p));
    return a;
}

__device__ __forceinline__ void cp_async16(uint32_t saddr, const void* g) {
    asm volatile("cp.async.cg.shared.global [%0], [%1], 16;"
                 :: "r"(saddr), "l"(g));
}
#define CP_COMMIT() asm volatile("cp.async.commit_group;" ::: "memory")
#define CP_WAIT1()  asm volatile("cp.async.wait_group 1;" ::: "memory")
#define CP_WAIT0()  asm volatile("cp.async.wait_group 0;" ::: "memory")

__device__ __forceinline__ void ldsm_x4(uint32_t (&r)[4], uint32_t addr) {
    asm volatile(
        "ldmatrix.sync.aligned.m8n8.x4.shared.b16 {%0,%1,%2,%3}, [%4];"
        : "=r"(r[0]), "=r"(r[1]), "=r"(r[2]), "=r"(r[3]) : "r"(addr));
}

__device__ __forceinline__ void ldsm_x2(uint32_t (&r)[2], uint32_t addr) {
    asm volatile(
        "ldmatrix.sync.aligned.m8n8.x2.shared.b16 {%0,%1}, [%2];"
        : "=r"(r[0]), "=r"(r[1]) : "r"(addr));
}

__device__ __forceinline__ void mma_bf16(float (&d)[4], const uint32_t (&a)[4],
                                         const uint32_t (&b)[2]) {
    asm volatile(
        "mma.sync.aligned.m16n8k16.row.col.f32.bf16.bf16.f32 "
        "{%0,%1,%2,%3}, {%4,%5,%6,%7}, {%8,%9}, {%0,%1,%2,%3};"
        : "+f"(d[0]), "+f"(d[1]), "+f"(d[2]), "+f"(d[3])
        : "r"(a[0]), "r"(a[1]), "r"(a[2]), "r"(a[3]), "r"(b[0]), "r"(b[1]));
}

__device__ __forceinline__ uint32_t pack_bf16(__nv_bfloat16 lo, __nv_bfloat16 hi) {
    __nv_bfloat162 t(lo, hi);
    return *(uint32_t*)&t;
}

// ---------------------------------------------------------------------------
// Split fp32 -> (hi, lo) bf16, elementwise (vectorized by 4)
// ---------------------------------------------------------------------------
__global__ __launch_bounds__(256) void split_convert_kernel(
    const float* __restrict__ in, __nv_bfloat16* __restrict__ hi,
    __nv_bfloat16* __restrict__ lo, int n4) {
    int i = blockIdx.x * blockDim.x + threadIdx.x;
    if (i >= n4) return;
    float4 x = ((const float4*)in)[i];
    __nv_bfloat16 h0 = __float2bfloat16(x.x);
    __nv_bfloat16 h1 = __float2bfloat16(x.y);
    __nv_bfloat16 h2 = __float2bfloat16(x.z);
    __nv_bfloat16 h3 = __float2bfloat16(x.w);
    __nv_bfloat16 l0 = __float2bfloat16(x.x - __bfloat162float(h0));
    __nv_bfloat16 l1 = __float2bfloat16(x.y - __bfloat162float(h1));
    __nv_bfloat16 l2 = __float2bfloat16(x.z - __bfloat162float(h2));
    __nv_bfloat16 l3 = __float2bfloat16(x.w - __bfloat162float(h3));
    __nv_bfloat162* hp = (__nv_bfloat162*)hi;
    __nv_bfloat162* lp = (__nv_bfloat162*)lo;
    hp[2 * i]     = __nv_bfloat162(h0, h1);
    hp[2 * i + 1] = __nv_bfloat162(h2, h3);
    lp[2 * i]     = __nv_bfloat162(l0, l1);
    lp[2 * i + 1] = __nv_bfloat162(l2, l3);
}

// ---------------------------------------------------------------------------
// Transpose + split (+ optional scale): in [K, N] fp32 -> hi/lo [N, K] bf16
// ---------------------------------------------------------------------------
__global__ __launch_bounds__(256) void transpose_split_kernel(
    const float* __restrict__ in, __nv_bfloat16* __restrict__ hi,
    __nv_bfloat16* __restrict__ lo, int K, int N, float scale) {
    __shared__ float t[32][33];
    int n0 = blockIdx.x * 32, k0 = blockIdx.y * 32;
    int tx = threadIdx.x, ty = threadIdx.y;
#pragma unroll
    for (int j = 0; j < 4; j++)
        t[ty + 8 * j][tx] = in[(size_t)(k0 + ty + 8 * j) * N + n0 + tx];
    __syncthreads();
#pragma unroll
    for (int j = 0; j < 4; j++) {
        float x = t[tx][ty + 8 * j] * scale;
        __nv_bfloat16 h = __float2bfloat16(x);
        __nv_bfloat16 l = __float2bfloat16(x - __bfloat162float(h));
        size_t o = (size_t)(n0 + ty + 8 * j) * K + k0 + tx;
        hi[o] = h;
        lo[o] = l;
    }
}

// ---------------------------------------------------------------------------
// mma.sync bf16 split-precision GEMM, cp.async double-buffered.
// Round-12 mainloop (per-ks fragment loop) + __launch_bounds__(256,2) to
// force 2 CTAs/SM (occ was 12.5%, issue 22% -> occupancy-bound).
// Epilogue: fp32 C (Chi==nullptr) or split-bf16 Chi/Clo.
// ---------------------------------------------------------------------------
#define SPAD 40
#define GARR (128 * SPAD)                    // bf16 elements per array
#define GEMM_SMEM (2 * 4 * GARR * 2)         // 81920 bytes

__global__ __launch_bounds__(256, 2) void mma_sync_gemm(
    const __nv_bfloat16* __restrict__ Ah, const __nv_bfloat16* __restrict__ Al,
    const __nv_bfloat16* __restrict__ Bh, const __nv_bfloat16* __restrict__ Bl,
    float* __restrict__ C, __nv_bfloat16* __restrict__ Chi,
    __nv_bfloat16* __restrict__ Clo, int Kd, int Nd) {
    extern __shared__ __align__(16) __nv_bfloat16 gsm[];

    const int tid = threadIdx.x;
    const int wid = tid / 32, lane = tid % 32;
    const int wm = wid / 4, wn = wid % 4;
    const int mBase = blockIdx.y * 128;
    const int nBase = blockIdx.x * 128;
    const int nChunks = Kd / 32;

    float acc[4][4][4];
#pragma unroll
    for (int i = 0; i < 4; i++)
#pragma unroll
        for (int j = 0; j < 4; j++)
#pragma unroll
            for (int r = 0; r < 4; r++) acc[i][j][r] = 0.0f;

    const int a_row = lane % 16, a_col8 = (lane / 16) * 8;
    const int b_row = lane % 8, b_col8 = ((lane % 16) / 8) * 8;

    auto load_stage = [&](int c, int s) {
        __nv_bfloat16* st = gsm + s * 4 * GARR;
        const int kBase = c * 32;
#pragma unroll
        for (int i = tid; i < 512; i += 256) {
            const int r = i >> 2, q = i & 3;
            const size_t ga = (size_t)(mBase + r) * Kd + kBase + q * 8;
            const size_t gb = (size_t)(nBase + r) * Kd + kBase + q * 8;
            const int so = r * SPAD + q * 8;
            cp_async16(smem_u32(&st[so]), &Ah[ga]);
            cp_async16(smem_u32(&st[GARR + so]), &Al[ga]);
            cp_async16(smem_u32(&st[2 * GARR + so]), &Bh[gb]);
            cp_async16(smem_u32(&st[3 * GARR + so]), &Bl[gb]);
        }
    };

    load_stage(0, 0);
    CP_COMMIT();

    for (int c = 0; c < nChunks; ++c) {
        if (c + 1 < nChunks) {
            load_stage(c + 1, (c + 1) & 1);
            CP_COMMIT();
            CP_WAIT1();
        } else {
            CP_WAIT0();
        }
        __syncthreads();

        const __nv_bfloat16* st = gsm + (c & 1) * 4 * GARR;
        const __nv_bfloat16* sAh = st;
        const __nv_bfloat16* sAl = st + GARR;
        const __nv_bfloat16* sBh = st + 2 * GARR;
        const __nv_bfloat16* sBl = st + 3 * GARR;

#pragma unroll
        for (int ks = 0; ks < 2; ++ks) {
            const int kk = ks * 16;
            uint32_t afh[4][4], afl[4][4];
#pragma unroll
            for (int mt = 0; mt < 4; mt++) {
                const int row = wm * 64 + mt * 16 + a_row;
                ldsm_x4(afh[mt], smem_u32(&sAh[row * SPAD + kk + a_col8]));
                ldsm_x4(afl[mt], smem_u32(&sAl[row * SPAD + kk + a_col8]));
            }
            uint32_t bfh[4][2], bfl[4][2];
#pragma unroll
            for (int nt = 0; nt < 4; nt++) {
                const int row = wn * 32 + nt * 8 + b_row;
                ldsm_x2(bfh[nt], smem_u32(&sBh[row * SPAD + kk + b_col8]));
                ldsm_x2(bfl[nt], smem_u32(&sBl[row * SPAD + kk + b_col8]));
            }
#pragma unroll
            for (int mt = 0; mt < 4; mt++)
#pragma unroll
                for (int nt = 0; nt < 4; nt++) {
                    mma_bf16(acc[mt][nt], afh[mt], bfh[nt]);
                    mma_bf16(acc[mt][nt], afh[mt], bfl[nt]);
                    mma_bf16(acc[mt][nt], afl[mt], bfh[nt]);
                }
        }
        __syncthreads();
    }

    const int em = lane / 4, en = 2 * (lane % 4);
    if (Chi == nullptr) {
#pragma unroll
        for (int mt = 0; mt < 4; mt++) {
#pragma unroll
            for (int nt = 0; nt < 4; nt++) {
                const int m0 = mBase + wm * 64 + mt * 16 + em;
                const int n0 = nBase + wn * 32 + nt * 8 + en;
                *(float2*)&C[(size_t)m0 * Nd + n0] =
                    make_float2(acc[mt][nt][0], acc[mt][nt][1]);
                *(float2*)&C[(size_t)(m0 + 8) * Nd + n0] =
                    make_float2(acc[mt][nt][2], acc[mt][nt][3]);
            }
        }
    } else {
#pragma unroll
        for (int mt = 0; mt < 4; mt++) {
#pragma unroll
            for (int nt = 0; nt < 4; nt++) {
                const int m0 = mBase + wm * 64 + mt * 16 + em;
                const int n0 = nBase + wn * 32 + nt * 8 + en;
                const float x0 = acc[mt][nt][0], x1 = acc[mt][nt][1];
                const float x2 = acc[mt][nt][2], x3 = acc[mt][nt][3];
                const __nv_bfloat16 h0 = __float2bfloat16(x0);
                const __nv_bfloat16 h1 = __float2bfloat16(x1);
                const __nv_bfloat16 h2 = __float2bfloat16(x2);
                const __nv_bfloat16 h3 = __float2bfloat16(x3);
                *(uint32_t*)&Chi[(size_t)m0 * Nd + n0] = pack_bf16(h0, h1);
                *(uint32_t*)&Chi[(size_t)(m0 + 8) * Nd + n0] = pack_bf16(h2, h3);
                *(uint32_t*)&Clo[(size_t)m0 * Nd + n0] =
                    pack_bf16(__float2bfloat16(x0 - __bfloat162float(h0)),
                              __float2bfloat16(x1 - __bfloat162float(h1)));
                *(uint32_t*)&Clo[(size_t)(m0 + 8) * Nd + n0] =
                    pack_bf16(__float2bfloat16(x2 - __bfloat162float(h2)),
                              __float2bfloat16(x3 - __bfloat162float(h3)));
            }
        }
    }
}

// ---------------------------------------------------------------------------
// Fused K/V projection (SIMT fp32) with split-bf16 epilogue.
// z=0: K@w_k -> khi/klo [b*SEQ][DK]
// z=1: V@w_v -> vthi/vtlo [b][DK][SEQ] (transposed for attention's P@V)
// ---------------------------------------------------------------------------
__global__ __launch_bounds__(128) void kv_proj_kernel(
    const float* __restrict__ Kin, const float* __restrict__ Vin,
    const float* __restrict__ w_k, const float* __restrict__ w_v,
    __nv_bfloat16* __restrict__ khi, __nv_bfloat16* __restrict__ klo,
    __nv_bfloat16* __restrict__ vthi, __nv_bfloat16* __restrict__ vtlo) {
    constexpr int BM = 128, BN = 64, BK = 8, TM = 8, TN = 8;
    constexpr int NT = (BM / TM) * (BN / TN);
    __shared__ float As[BK][BM];
    __shared__ float Bs[BK][BN];

    const int isV = blockIdx.z;
    const float* A  = isV ? Vin : Kin;
    const float* Bm = isV ? w_v : w_k;

    const int tid = threadIdx.x;
    const int tx = tid % (BN / TN);
    const int ty = tid / (BN / TN);
    const int mBase = blockIdx.y * BM;
    const int K = DM, Nn = DK;

    float acc[TM][TN];
#pragma unroll
    for (int i = 0; i < TM; i++)
#pragma unroll
        for (int j = 0; j < TN; j++) acc[i][j] = 0.0f;

    for (int k0 = 0; k0 < K; k0 += BK) {
#pragma unroll
        for (int i = tid; i < BM * BK / 4; i += NT) {
            int r = i / (BK / 4);
            int c4 = i % (BK / 4);
            float4 a = *(const float4*)&A[(size_t)(mBase + r) * K + k0 + c4 * 4];
            As[c4 * 4 + 0][r] = a.x;
            As[c4 * 4 + 1][r] = a.y;
            As[c4 * 4 + 2][r] = a.z;
            As[c4 * 4 + 3][r] = a.w;
        }
#pragma unroll
        for (int i = tid; i < BK * BN / 4; i += NT) {
            int r = i / (BN / 4);
            int c4 = i % (BN / 4);
            *(float4*)&Bs[r][c4 * 4] =
                *(const float4*)&Bm[(size_t)(k0 + r) * Nn + c4 * 4];
        }
        __syncthreads();

#pragma unroll
        for (int kk = 0; kk < BK; kk++) {
            float ra[TM], rb[TN];
#pragma unroll
            for (int i = 0; i < TM; i++) ra[i] = As[kk][ty * TM + i];
#pragma unroll
            for (int j = 0; j < TN; j++) rb[j] = Bs[kk][tx * TN + j];
#pragma unroll
            for (int i = 0; i < TM; i++)
#pragma unroll
                for (int j = 0; j < TN; j++) acc[i][j] += ra[i] * rb[j];
        }
        __syncthreads();
    }

    // split-bf16 epilogue (K row-major; V transposed)
#pragma unroll
    for (int i = 0; i < TM; i++) {
        const int s = mBase + ty * TM + i;       // global row: b*SEQ + n
#pragma unroll
        for (int j = 0; j < TN; j++) {
            const int col = tx * TN + j;         // dk index
            const float x = acc[i][j];
            const __nv_bfloat16 hv = __float2bfloat16(x);
            const __nv_bfloat16 lv = __float2bfloat16(x - __bfloat162float(hv));
            if (!isV) {
                khi[(size_t)s * DK + col] = hv;
                klo[(size_t)s * DK + col] = lv;
            } else {
                const int bb = s / SEQ, n = s % SEQ;
                vthi[((size_t)bb * DK + col) * SEQ + n] = hv;
                vtlo[((size_t)bb * DK + col) * SEQ + n] = lv;
            }
        }
    }
}

// ---------------------------------------------------------------------------
// Causal MQA flash attention (mma.sync, split-bf16), cp.async double-buffered
// K/V tiles, pre-split Q (scale folded into w_q). Writes split-bf16 ahi/alo.
// ---------------------------------------------------------------------------
#define APAD 72
#define KVARR (64 * APAD)                              // bf16 per array
#define Q_BYTES (2 * 128 * APAD * 2)                   // 36864
#define ATTN_SMEM (Q_BYTES + 2 * 4 * KVARR * 2)        // 110592

__global__ __launch_bounds__(256, 1) void mqa_attn_mma(
    const __nv_bfloat16* __restrict__ qhi, const __nv_bfloat16* __restrict__ qlo,
    const __nv_bfloat16* __restrict__ khi, const __nv_bfloat16* __restrict__ klo,
    const __nv_bfloat16* __restrict__ vthi, const __nv_bfloat16* __restrict__ vtlo,
    __nv_bfloat16* __restrict__ outhi, __nv_bfloat16* __restrict__ outlo) {
    extern __shared__ __align__(16) char smem_raw[];
    __nv_bfloat16* sQh = (__nv_bfloat16*)smem_raw;
    __nv_bfloat16* sQl = sQh + 128 * APAD;
    __nv_bfloat16* sKV = sQl + 128 * APAD;  // 2 stages x {Kh, Kl, Vh, Vl}

    const int qt = gridDim.x - 1 - blockIdx.x;  // heavy qtiles first
    const int h = blockIdx.y, b = blockIdx.z;
    const int tid = threadIdx.x, wid = tid / 32, lane = tid % 32;
    const int rowBase = qt * 128;
    const int wRow = wid * 16;

    // ---- copy pre-split Q slice [128][64] (scale already folded) ----
    {
        const __nv_bfloat16* qh = &qhi[((size_t)b * SEQ + rowBase) * DM + h * DK];
        const __nv_bfloat16* ql = &qlo[((size_t)b * SEQ + rowBase) * DM + h * DK];
#pragma unroll
        for (int i = tid; i < 1024; i += 256) {
            const int r = i >> 3, c = (i & 7) * 8;
            *(uint4*)&sQh[r * APAD + c] = *(const uint4*)&qh[(size_t)r * DM + c];
            *(uint4*)&sQl[r * APAD + c] = *(const uint4*)&ql[(size_t)r * DM + c];
        }
    }

    // async-load K/V tile t into stage s (no sync here)
    auto load_kv = [&](int t, int s) {
        __nv_bfloat16* st = sKV + s * 4 * KVARR;
        const __nv_bfloat16* kh = &khi[((size_t)b * SEQ + t * 64) * DK];
        const __nv_bfloat16* kl = &klo[((size_t)b * SEQ + t * 64) * DK];
        const __nv_bfloat16* vh = &vthi[(size_t)b * DK * SEQ + t * 64];
        const __nv_bfloat16* vl = &vtlo[(size_t)b * DK * SEQ + t * 64];
#pragma unroll
        for (int i = tid; i < 512; i += 256) {
            const int r = i >> 3, c = (i & 7) * 8;
            const int so = r * APAD + c;
            cp_async16(smem_u32(&st[so]), &kh[r * DK + c]);
            cp_async16(smem_u32(&st[KVARR + so]), &kl[r * DK + c]);
            cp_async16(smem_u32(&st[2 * KVARR + so]), &vh[(size_t)r * SEQ + c]);
            cp_async16(smem_u32(&st[3 * KVARR + so]), &vl[(size_t)r * SEQ + c]);
        }
    };

    const int nT = 2 * qt + 2;
    load_kv(0, 0);
    CP_COMMIT();
    __syncthreads();  // Q smem ready for all warps

    // ---- preload Q fragments for all 4 k-steps ----
    uint32_t qfh[4][4], qfl[4][4];
    {
        const int rr = wRow + (lane & 7) + ((lane >> 3) & 1) * 8;
        const int cc = (lane >> 4) * 8;
#pragma unroll
        for (int ks = 0; ks < 4; ks++) {
            ldsm_x4(qfh[ks], smem_u32(&sQh[rr * APAD + ks * 16 + cc]));
            ldsm_x4(qfl[ks], smem_u32(&sQl[rr * APAD + ks * 16 + cc]));
        }
    }

    float oacc[8][4];
#pragma unroll
    for (int nt = 0; nt < 8; nt++)
#pragma unroll
        for (int j = 0; j < 4; j++) oacc[nt][j] = 0.0f;
    float m0 = -6e29f, m1 = -6e29f, l0 = 0.0f, l1 = 0.0f;

    const int bRowK = (lane & 7);
    const int bColK = ((lane >> 3) & 1) * 8;

    for (int t = 0; t < nT; ++t) {
        if (t + 1 < nT) {
            load_kv(t + 1, (t + 1) & 1);
            CP_COMMIT();
            CP_WAIT1();
        } else {
            CP_WAIT0();
        }
        __syncthreads();

        const __nv_bfloat16* st = sKV + (t & 1) * 4 * KVARR;
        const __nv_bfloat16* sKh = st;
        const __nv_bfloat16* sKl = st + KVARR;
        const __nv_bfloat16* sVh = st + 2 * KVARR;
        const __nv_bfloat16* sVl = st + 3 * KVARR;

        // ---- S = Q @ K^T (split, 3 terms) ----
        float sacc[8][4];
#pragma unroll
        for (int nt = 0; nt < 8; nt++)
#pragma unroll
            for (int j = 0; j < 4; j++) sacc[nt][j] = 0.0f;
#pragma unroll
        for (int ks = 0; ks < 4; ks++) {
#pragma unroll
            for (int nt = 0; nt < 8; nt++) {
                uint32_t kbh[2], kbl[2];
                ldsm_x2(kbh, smem_u32(&sKh[(nt * 8 + bRowK) * APAD + ks * 16 + bColK]));
                ldsm_x2(kbl, smem_u32(&sKl[(nt * 8 + bRowK) * APAD + ks * 16 + bColK]));
                mma_bf16(sacc[nt], qfh[ks], kbh);
                mma_bf16(sacc[nt], qfh[ks], kbl);
                mma_bf16(sacc[nt], qfl[ks], kbh);
            }
        }

        // ---- causal mask (only near-diagonal tiles) ----
        if (64 * t + 63 > rowBase + wRow) {
            const int r0 = rowBase + wRow + (lane >> 2);
#pragma unroll
            for (int nt = 0; nt < 8; nt++) {
                const int col = 64 * t + nt * 8 + 2 * (lane & 3);
                if (col > r0) sacc[nt][0] = -1e30f;
                if (col + 1 > r0) sacc[nt][1] = -1e30f;
                if (col > r0 + 8) sacc[nt][2] = -1e30f;
                if (col + 1 > r0 + 8) sacc[nt][3] = -1e30f;
            }
        }

        // ---- online softmax in fragments ----
        float rm0 = -1e30f, rm1 = -1e30f;
#pragma unroll
        for (int nt = 0; nt < 8; nt++) {
            rm0 = fmaxf(rm0, fmaxf(sacc[nt][0], sacc[nt][1]));
            rm1 = fmaxf(rm1, fmaxf(sacc[nt][2], sacc[nt][3]));
        }
        rm0 = fmaxf(rm0, __shfl_xor_sync(0xffffffffu, rm0, 1));
        rm0 = fmaxf(rm0, __shfl_xor_sync(0xffffffffu, rm0, 2));
        rm1 = fmaxf(rm1, __shfl_xor_sync(0xffffffffu, rm1, 1));
        rm1 = fmaxf(rm1, __shfl_xor_sync(0xffffffffu, rm1, 2));
        const float mn0 = fmaxf(m0, rm0), mn1 = fmaxf(m1, rm1);
        const float c0 = ex2_fast(m0 - mn0), c1 = ex2_fast(m1 - mn1);
        m0 = mn0; m1 = mn1;
        l0 *= c0; l1 *= c1;
#pragma unroll
        for (int nt = 0; nt < 8; nt++) {
            oacc[nt][0] *= c0; oacc[nt][1] *= c0;
            oacc[nt][2] *= c1; oacc[nt][3] *= c1;
        }

        uint32_t php[8][2], plp[8][2];
#pragma unroll
        for (int nt = 0; nt < 8; nt++) {
            const float p0 = ex2_fast(sacc[nt][0] - m0);
            const float p1 = ex2_fast(sacc[nt][1] - m0);
            const float p2 = ex2_fast(sacc[nt][2] - m1);
            const float p3 = ex2_fast(sacc[nt][3] - m1);
            l0 += p0 + p1;
            l1 += p2 + p3;
            const __nv_bfloat16 b0 = __float2bfloat16(p0), b1 = __float2bfloat16(p1);
            const __nv_bfloat16 b2 = __float2bfloat16(p2), b3 = __float2bfloat16(p3);
            php[nt][0] = pack_bf16(b0, b1);
            php[nt][1] = pack_bf16(b2, b3);
            plp[nt][0] = pack_bf16(__float2bfloat16(p0 - __bfloat162float(b0)),
                                   __float2bfloat16(p1 - __bfloat162float(b1)));
            plp[nt][1] = pack_bf16(__float2bfloat16(p2 - __bfloat162float(b2)),
                                   __float2bfloat16(p3 - __bfloat162float(b3)));
        }

        // ---- O += P @ V (split, 3 terms) ----
#pragma unroll
        for (int t2 = 0; t2 < 4; t2++) {
            const uint32_t ah[4] = {php[2 * t2][0], php[2 * t2][1],
                                    php[2 * t2 + 1][0], php[2 * t2 + 1][1]};
            const uint32_t al[4] = {plp[2 * t2][0], plp[2 * t2][1],
                                    plp[2 * t2 + 1][0], plp[2 * t2 + 1][1]};
#pragma unroll
            for (int ntd = 0; ntd < 8; ntd++) {
                uint32_t vbh[2], vbl[2];
                ldsm_x2(vbh, smem_u32(&sVh[(ntd * 8 + bRowK) * APAD + t2 * 16 + bColK]));
                ldsm_x2(vbl, smem_u32(&sVl[(ntd * 8 + bRowK) * APAD + t2 * 16 + bColK]));
                mma_bf16(oacc[ntd], ah, vbh);
                mma_bf16(oacc[ntd], ah, vbl);
                mma_bf16(oacc[ntd], al, vbh);
            }
        }
        __syncthreads();  // all warps done with this stage before it is reused
    }

    // ---- finalize: reduce l, normalize, write split-bf16 directly ----
    l0 += __shfl_xor_sync(0xffffffffu, l0, 1);
    l0 += __shfl_xor_sync(0xffffffffu, l0, 2);
    l1 += __shfl_xor_sync(0xffffffffu, l1, 1);
    l1 += __shfl_xor_sync(0xffffffffu, l1, 2);
    const float inv0 = 1.0f / l0, inv1 = 1.0f / l1;
    const int r0 = rowBase + wRow + (lane >> 2);
    const int cb = h * DK + 2 * (lane & 3);
#pragma unroll
    for (int nt = 0; nt < 8; nt++) {
        const float x0 = oacc[nt][0] * inv0, x1 = oacc[nt][1] * inv0;
        const float x2 = oacc[nt][2] * inv1, x3 = oacc[nt][3] * inv1;
        const __nv_bfloat16 h0 = __float2bfloat16(x0), h1 = __float2bfloat16(x1);
        const __nv_bfloat16 h2 = __float2bfloat16(x2), h3 = __float2bfloat16(x3);
        const size_t i0 = ((size_t)b * SEQ + r0) * DM + cb + nt * 8;
        const size_t i1 = ((size_t)b * SEQ + r0 + 8) * DM + cb + nt * 8;
        *(uint32_t*)&outhi[i0] = pack_bf16(h0, h1);
        *(uint32_t*)&outhi[i1] = pack_bf16(h2, h3);
        *(uint32_t*)&outlo[i0] =
            pack_bf16(__float2bfloat16(x0 - __bfloat162float(h0)),
                      __float2bfloat16(x1 - __bfloat162float(h1)));
        *(uint32_t*)&outlo[i1] =
            pack_bf16(__float2bfloat16(x2 - __bfloat162float(h2)),
                      __float2bfloat16(x3 - __bfloat162float(h3)));
    }
}

// ---------------------------------------------------------------------------
extern "C" void kernel_launch(void* const* d_in, const int* in_sizes, int n_in,
                              void* d_out, int out_size) {
    const float* Q   = (const float*)d_in[0];
    const float* K   = (const float*)d_in[1];
    const float* V   = (const float*)d_in[2];
    const float* w_q = (const float*)d_in[3];
    const float* w_k = (const float*)d_in[4];
    const float* w_v = (const float*)d_in[5];
    const float* w_o = (const float*)d_in[6];
    float* out = (float*)d_out;

    __nv_bfloat16 *qhi, *qlo, *khi, *klo, *vthi, *vtlo, *ahi, *alo;
    __nv_bfloat16 *wqh, *wql, *woh, *wol;
    cudaGetSymbolAddress((void**)&qhi, g_qhi);
    cudaGetSymbolAddress((void**)&qlo, g_qlo);
    cudaGetSymbolAddress((void**)&khi, g_khi);
    cudaGetSymbolAddress((void**)&klo, g_klo);
    cudaGetSymbolAddress((void**)&vthi, g_vthi);
    cudaGetSymbolAddress((void**)&vtlo, g_vtlo);
    cudaGetSymbolAddress((void**)&ahi, g_ahi);
    cudaGetSymbolAddress((void**)&alo, g_alo);
    cudaGetSymbolAddress((void**)&wqh, g_wqt_hi);
    cudaGetSymbolAddress((void**)&wql, g_wqt_lo);
    cudaGetSymbolAddress((void**)&woh, g_wot_hi);
    cudaGetSymbolAddress((void**)&wol, g_wot_lo);

    cudaFuncSetAttribute(mma_sync_gemm,
                         cudaFuncAttributeMaxDynamicSharedMemorySize, GEMM_SMEM);
    cudaFuncSetAttribute(mqa_attn_mma,
                         cudaFuncAttributeMaxDynamicSharedMemorySize, ATTN_SMEM);

    const int M = BATCH * SEQ;      // 8192
    const int n4 = M * DM / 4;
    const float sc = 0.125f * 1.44269504088896f;  // 1/sqrt(64) * log2(e)

    // weight transpose + split; softmax scale folded into w_q
    transpose_split_kernel<<<dim3(DM / 32, DM / 32), dim3(32, 8)>>>(
        w_q, wqh, wql, DM, DM, sc);
    transpose_split_kernel<<<dim3(DM / 32, DM / 32), dim3(32, 8)>>>(
        w_o, woh, wol, DM, DM, 1.0f);

    // Q projection (tensor cores): split Q input, MMA -> split qhi/qlo
    split_convert_kernel<<<n4 / 256, 256>>>(Q, ahi, alo, n4);
    mma_sync_gemm<<<dim3(DM / 128, M / 128), 256, GEMM_SMEM>>>(
        ahi, alo, wqh, wql, nullptr, qhi, qlo, DM, DM);

    // K/V projections (SIMT fp32) with fused split / transpose epilogue
    kv_proj_kernel<<<dim3(1, M / 128, 2), 128>>>(K, V, w_k, w_v,
                                                 khi, klo, vthi, vtlo);

    // causal MQA attention on tensor cores; writes split-bf16 ahi/alo
    mqa_attn_mma<<<dim3(SEQ / 128, NH, BATCH), 256, ATTN_SMEM>>>(
        qhi, qlo, khi, klo, vthi, vtlo, ahi, alo);

    // O projection (tensor cores) -> fp32 d_out
    mma_sync_gemm<<<dim3(DM / 128, M / 128), 256, GEMM_SMEM>>>(
        ahi, alo, woh, wol, out, nullptr, nullptr, DM, DM);
}